// round 1
// baseline (speedup 1.0000x reference)
#include <cuda_runtime.h>

// Problem constants
#define BB 2
#define TT 1024          // query length
#define MM 1024          // memory length
#define LL 2048          // key length = M+T
#define JJ 2048          // pos length = M+T
#define HH 16
#define DH 64
#define DM 1024
#define SCALE_F 0.125f   // 1/sqrt(64)

// -------- scratch (device globals; no allocation allowed) --------
__device__ float g_qraw[BB * TT * DM];                   // x @ q_w.T
__device__ float g_qu  [BB * TT * DM];                   // q + pos_bias_u
__device__ float g_qv  [BB * TT * DM];                   // q + pos_bias_v
__device__ float g_kraw[BB * LL * DM];                   // cat @ k_w.T
__device__ float g_vraw[BB * LL * DM];                   // cat @ v_w.T
__device__ float g_rraw[JJ * DM];                        // pos_emb @ r_w.T
__device__ float g_scores[(size_t)BB * HH * TT * LL];    // content scores -> probs
__device__ float g_rel   [(size_t)BB * HH * TT * JJ];    // rel scores (pre-shift)
__device__ float g_ctx [BB * TT * DM];                   // attn output, [B,T,D]

// ---------------------------------------------------------------------------
// Tiled GEMM, NT form: C[m,n] = sum_k A[m,k] * B[n,k]
// 64x64 tile, BK=16, 256 threads, 4x4 micro-tile per thread.
// Per-z offsets: off = (z/zdiv)*Outer + (z%zdiv)*Inner for each of A, B, C.
// All dims assumed multiples of 64 (true for this problem), K multiple of 16.
// ---------------------------------------------------------------------------
__global__ __launch_bounds__(256) void gemm_nt(
    const float* __restrict__ A, int lda, long aO, long aI,
    const float* __restrict__ B, int ldb, long bO, long bI,
    float* __restrict__ C, int ldc, long cO, long cI,
    int K, int zdiv)
{
    int z = blockIdx.z;
    long zo = z / zdiv, zi = z % zdiv;
    A += zo * aO + zi * aI;
    B += zo * bO + zi * bI;
    C += zo * cO + zi * cI;

    __shared__ float As[16][64];
    __shared__ float Bs[16][64];

    int tid = threadIdx.x;
    int tx = tid & 15;          // micro-tile col group
    int ty = tid >> 4;          // micro-tile row group
    int lr = tid >> 2;          // 0..63 loader row
    int lc = (tid & 3) << 2;    // 0,4,8,12 loader k-offset

    const float* Ap = A + (long)(blockIdx.y * 64 + lr) * lda + lc;
    const float* Bp = B + (long)(blockIdx.x * 64 + lr) * ldb + lc;

    float acc[4][4] = {};

    for (int k0 = 0; k0 < K; k0 += 16) {
        float4 a4 = *(const float4*)(Ap + k0);
        float4 b4 = *(const float4*)(Bp + k0);
        __syncthreads();
        As[lc + 0][lr] = a4.x; As[lc + 1][lr] = a4.y;
        As[lc + 2][lr] = a4.z; As[lc + 3][lr] = a4.w;
        Bs[lc + 0][lr] = b4.x; Bs[lc + 1][lr] = b4.y;
        Bs[lc + 2][lr] = b4.z; Bs[lc + 3][lr] = b4.w;
        __syncthreads();
#pragma unroll
        for (int kk = 0; kk < 16; kk++) {
            float av[4], bv[4];
#pragma unroll
            for (int i = 0; i < 4; i++) av[i] = As[kk][ty * 4 + i];
#pragma unroll
            for (int j = 0; j < 4; j++) bv[j] = Bs[kk][tx * 4 + j];
#pragma unroll
            for (int i = 0; i < 4; i++)
#pragma unroll
                for (int j = 0; j < 4; j++)
                    acc[i][j] += av[i] * bv[j];
        }
    }
#pragma unroll
    for (int i = 0; i < 4; i++) {
        float* Crow = C + (long)(blockIdx.y * 64 + ty * 4 + i) * ldc
                        + blockIdx.x * 64 + tx * 4;
        float4 v = make_float4(acc[i][0], acc[i][1], acc[i][2], acc[i][3]);
        *(float4*)Crow = v;
    }
}

// ---------------------------------------------------------------------------
// Tiled GEMM, NN form: C[m,n] = sum_k A[m,k] * B[k,n]   (for attn @ V)
// ---------------------------------------------------------------------------
__global__ __launch_bounds__(256) void gemm_nn(
    const float* __restrict__ A, int lda, long aO, long aI,
    const float* __restrict__ B, int ldb, long bO, long bI,
    float* __restrict__ C, int ldc, long cO, long cI,
    int K, int zdiv)
{
    int z = blockIdx.z;
    long zo = z / zdiv, zi = z % zdiv;
    A += zo * aO + zi * aI;
    B += zo * bO + zi * bI;
    C += zo * cO + zi * cI;

    __shared__ float As[16][64];
    __shared__ float Bs[16][64];

    int tid = threadIdx.x;
    int tx = tid & 15;
    int ty = tid >> 4;
    int lr = tid >> 2;          // A loader: row 0..63
    int lc = (tid & 3) << 2;    // A loader: k offset
    int brow = tid >> 4;        // B loader: k 0..15
    int bcol = (tid & 15) << 2; // B loader: n offset

    const float* Ap = A + (long)(blockIdx.y * 64 + lr) * lda + lc;
    const float* Bbase = B + blockIdx.x * 64 + bcol;

    float acc[4][4] = {};

    for (int k0 = 0; k0 < K; k0 += 16) {
        float4 a4 = *(const float4*)(Ap + k0);
        float4 b4 = *(const float4*)(Bbase + (long)(k0 + brow) * ldb);
        __syncthreads();
        As[lc + 0][lr] = a4.x; As[lc + 1][lr] = a4.y;
        As[lc + 2][lr] = a4.z; As[lc + 3][lr] = a4.w;
        Bs[brow][bcol + 0] = b4.x; Bs[brow][bcol + 1] = b4.y;
        Bs[brow][bcol + 2] = b4.z; Bs[brow][bcol + 3] = b4.w;
        __syncthreads();
#pragma unroll
        for (int kk = 0; kk < 16; kk++) {
            float av[4], bv[4];
#pragma unroll
            for (int i = 0; i < 4; i++) av[i] = As[kk][ty * 4 + i];
#pragma unroll
            for (int j = 0; j < 4; j++) bv[j] = Bs[kk][tx * 4 + j];
#pragma unroll
            for (int i = 0; i < 4; i++)
#pragma unroll
                for (int j = 0; j < 4; j++)
                    acc[i][j] += av[i] * bv[j];
        }
    }
#pragma unroll
    for (int i = 0; i < 4; i++) {
        float* Crow = C + (long)(blockIdx.y * 64 + ty * 4 + i) * ldc
                        + blockIdx.x * 64 + tx * 4;
        float4 v = make_float4(acc[i][0], acc[i][1], acc[i][2], acc[i][3]);
        *(float4*)Crow = v;
    }
}

// q + pos_bias_u / q + pos_bias_v (bias flattened [16,64] == column index % 1024)
__global__ void add_bias2(const float* __restrict__ q,
                          const float* __restrict__ u,
                          const float* __restrict__ v,
                          float* __restrict__ qu, float* __restrict__ qv, int n)
{
    int i = blockIdx.x * blockDim.x + threadIdx.x;
    if (i < n) {
        float b = q[i];
        int c = i & (DM - 1);
        qu[i] = b + u[c];
        qv[i] = b + v[c];
    }
}

// Fused rel-shift gather + scale + softmax. One block per (b,h,i) row.
// shifted[i,l] = pad[(i*J + l + T) / (J+1), (i*J + l + T) % (J+1)]
// where pad[r,0] = 0, pad[r,c] = rel[r, c-1].
__global__ __launch_bounds__(256) void softmax_shift(
    float* __restrict__ scores, const float* __restrict__ rel)
{
    int row = blockIdx.x;              // z*T + i, z = b*H+h
    int z = row >> 10;
    int i = row & (TT - 1);
    float* crow = scores + (size_t)row * LL;
    const float* rz = rel + (size_t)z * TT * JJ;

    int tid = threadIdx.x;
    float vals[8];
    float mx = -1e30f;
#pragma unroll
    for (int t = 0; t < 8; t++) {
        int l = tid + t * 256;
        long idx = (long)i * JJ + l + TT;
        int rr = (int)(idx / (JJ + 1));
        int cc = (int)(idx - (long)rr * (JJ + 1));
        float rv = (cc != 0) ? rz[(size_t)rr * JJ + (cc - 1)] : 0.0f;
        float s = (crow[l] + rv) * SCALE_F;
        vals[t] = s;
        mx = fmaxf(mx, s);
    }

    __shared__ float red[256];
    red[tid] = mx;
    __syncthreads();
    for (int s = 128; s > 0; s >>= 1) {
        if (tid < s) red[tid] = fmaxf(red[tid], red[tid + s]);
        __syncthreads();
    }
    mx = red[0];
    __syncthreads();

    float sum = 0.0f;
#pragma unroll
    for (int t = 0; t < 8; t++) {
        vals[t] = __expf(vals[t] - mx);
        sum += vals[t];
    }
    red[tid] = sum;
    __syncthreads();
    for (int s = 128; s > 0; s >>= 1) {
        if (tid < s) red[tid] += red[tid + s];
        __syncthreads();
    }
    float inv = 1.0f / red[0];
#pragma unroll
    for (int t = 0; t < 8; t++) {
        int l = tid + t * 256;
        crow[l] = vals[t] * inv;
    }
}

extern "C" void kernel_launch(void* const* d_in, const int* in_sizes, int n_in,
                              void* d_out, int out_size)
{
    (void)in_sizes; (void)n_in; (void)out_size;
    const float* x      = (const float*)d_in[0];
    const float* memory = (const float*)d_in[1];
    const float* pos    = (const float*)d_in[2];
    const float* q_w    = (const float*)d_in[3];
    const float* k_w    = (const float*)d_in[4];
    const float* v_w    = (const float*)d_in[5];
    const float* r_w    = (const float*)d_in[6];
    const float* out_w  = (const float*)d_in[7];
    const float* pb_u   = (const float*)d_in[8];
    const float* pb_v   = (const float*)d_in[9];
    float* out = (float*)d_out;

    float *qraw, *qu, *qv, *kraw, *vraw, *rraw, *scores, *rel, *ctx;
    cudaGetSymbolAddress((void**)&qraw,   g_qraw);
    cudaGetSymbolAddress((void**)&qu,     g_qu);
    cudaGetSymbolAddress((void**)&qv,     g_qv);
    cudaGetSymbolAddress((void**)&kraw,   g_kraw);
    cudaGetSymbolAddress((void**)&vraw,   g_vraw);
    cudaGetSymbolAddress((void**)&rraw,   g_rraw);
    cudaGetSymbolAddress((void**)&scores, g_scores);
    cudaGetSymbolAddress((void**)&rel,    g_rel);
    cudaGetSymbolAddress((void**)&ctx,    g_ctx);

    const long TD = (long)TT * DM;   // 1M
    const long LD = (long)LL * DM;   // 2M
    const long TL = (long)TT * LL;   // 2M

    // 1) Q projection: [2048,1024] = x @ q_w.T
    gemm_nt<<<dim3(DM / 64, (BB * TT) / 64, 1), 256>>>(
        x, DM, 0, 0,  q_w, DM, 0, 0,  qraw, DM, 0, 0,  DM, 1);

    // 2) K projection over cat = [memory; x] per batch
    gemm_nt<<<dim3(DM / 64, MM / 64, BB), 256>>>(
        memory, DM, (long)MM * DM, 0,  k_w, DM, 0, 0,
        kraw, DM, LD, 0,  DM, 1);
    gemm_nt<<<dim3(DM / 64, TT / 64, BB), 256>>>(
        x, DM, TD, 0,  k_w, DM, 0, 0,
        kraw + (long)MM * DM, DM, LD, 0,  DM, 1);

    // 3) V projection over cat
    gemm_nt<<<dim3(DM / 64, MM / 64, BB), 256>>>(
        memory, DM, (long)MM * DM, 0,  v_w, DM, 0, 0,
        vraw, DM, LD, 0,  DM, 1);
    gemm_nt<<<dim3(DM / 64, TT / 64, BB), 256>>>(
        x, DM, TD, 0,  v_w, DM, 0, 0,
        vraw + (long)MM * DM, DM, LD, 0,  DM, 1);

    // 4) R projection: [2048,1024] = pos_emb @ r_w.T
    gemm_nt<<<dim3(DM / 64, JJ / 64, 1), 256>>>(
        pos, DM, 0, 0,  r_w, DM, 0, 0,  rraw, DM, 0, 0,  DM, 1);

    // 5) q_u = q + u, q_v = q + v
    add_bias2<<<(BB * TT * DM) / 256, 256>>>(qraw, pb_u, pb_v, qu, qv, BB * TT * DM);

    // 6) content scores: per (b,h): [1024,2048] = (q+u) @ k^T
    gemm_nt<<<dim3(LL / 64, TT / 64, BB * HH), 256>>>(
        qu,   DM, TD, 64,
        kraw, DM, LD, 64,
        scores, LL, (long)HH * TL, TL,
        DH, HH);

    // 7) rel scores: per (b,h): [1024,2048] = (q+v) @ r^T (r shared across b)
    gemm_nt<<<dim3(JJ / 64, TT / 64, BB * HH), 256>>>(
        qv,   DM, TD, 64,
        rraw, DM, 0,  64,
        rel, JJ, (long)HH * TL, TL,
        DH, HH);

    // 8) rel-shift + scale + softmax (in place on scores)
    softmax_shift<<<BB * HH * TT, 256>>>(scores, rel);

    // 9) ctx = attn @ V : per (b,h): [1024,64], written into [B,T,D] layout
    gemm_nn<<<dim3(1, TT / 64, BB * HH), 256>>>(
        scores, LL, (long)HH * TL, TL,
        vraw,   DM, LD, 64,
        ctx,    DM, TD, 64,
        LL, HH);

    // 10) output projection: [2048,1024] = ctx @ out_w.T
    gemm_nt<<<dim3(DM / 64, (BB * TT) / 64, 1), 256>>>(
        ctx, DM, 0, 0,  out_w, DM, 0, 0,  out, DM, 0, 0,  DM, 1);
}

// round 3
// speedup vs baseline: 2.6624x; 2.6624x over previous
#include <cuda_runtime.h>
#include <cstdint>

#define BB 2
#define TT 1024
#define MM 1024
#define LL 2048
#define JJ 2048
#define HH 16
#define DH 64
#define DM 1024
#define SCALE_F 0.125f

// -------- scratch (device globals; no allocation allowed) --------
__device__ float g_qraw[BB * TT * DM];
__device__ float g_qu  [BB * TT * DM];
__device__ float g_qv  [BB * TT * DM];
__device__ float g_kraw[BB * LL * DM];
__device__ float g_vraw[BB * LL * DM];
__device__ float g_rraw[JJ * DM];
__device__ float g_scores[(size_t)BB * HH * TT * LL];
__device__ float g_rel   [(size_t)BB * HH * TT * JJ];
__device__ float g_ctx [BB * TT * DM];

__device__ __forceinline__ unsigned f2tf32(float f) {
    unsigned u;
    asm("cvt.rna.tf32.f32 %0, %1;" : "=r"(u) : "f"(f));
    return u;
}

__device__ __forceinline__ void mma_tf32(float& c0, float& c1, float& c2, float& c3,
                                         unsigned a0, unsigned a1, unsigned a2, unsigned a3,
                                         unsigned b0, unsigned b1) {
    asm volatile(
        "mma.sync.aligned.m16n8k8.row.col.f32.tf32.tf32.f32 "
        "{%0,%1,%2,%3}, {%4,%5,%6,%7}, {%8,%9}, {%0,%1,%2,%3};"
        : "+f"(c0), "+f"(c1), "+f"(c2), "+f"(c3)
        : "r"(a0), "r"(a1), "r"(a2), "r"(a3), "r"(b0), "r"(b1));
}

// ---------------------------------------------------------------------------
// tf32 MMA GEMM, NT: C[m,n] = sum_k A[m,k]*B[n,k].  BM=128 BN=64 BK=32.
// 256 threads, 8 warps in 4(M)x2(N), warp tile 32x32 = 2 m-frags x 4 n-frags.
// Smem strides 36 (==4 mod 32) -> conflict-free fragment loads.
// ---------------------------------------------------------------------------
#define AST 36
#define BST 36
#define BSTN 68

__global__ __launch_bounds__(256, 2) void gemm_nt_tc(
    const float* __restrict__ A, int lda, long aO, long aI,
    const float* __restrict__ B, int ldb, long bO, long bI,
    float* __restrict__ C, int ldc, long cO, long cI,
    int K, int zdiv)
{
    int z = blockIdx.z;
    long zo = z / zdiv, zi = z % zdiv;
    A += zo * aO + zi * aI;
    B += zo * bO + zi * bI;
    C += zo * cO + zi * cI;

    __shared__ unsigned As[128 * AST];
    __shared__ unsigned Bs[64 * BST];

    const int tid  = threadIdx.x;
    const int warp = tid >> 5;
    const int lane = tid & 31;
    const int g = lane >> 2;      // group id 0..7
    const int t = lane & 3;       // thread-in-group 0..3
    const int wm = warp >> 1;     // 0..3  -> m offset wm*32
    const int wn = warp & 1;      // 0..1  -> n offset wn*32

    // loaders
    const int ar = tid >> 1;             // A row helper: idx = tid + i*256; row=idx>>3
    (void)ar;
    float4 la[4], lb[2];

    const int m0 = blockIdx.y * 128;
    const int n0 = blockIdx.x * 64;

    // preload tile 0
#pragma unroll
    for (int i = 0; i < 4; i++) {
        int idx = tid + i * 256;
        la[i] = *(const float4*)(A + (long)(m0 + (idx >> 3)) * lda + ((idx & 7) << 2));
    }
#pragma unroll
    for (int i = 0; i < 2; i++) {
        int idx = tid + i * 256;
        lb[i] = *(const float4*)(B + (long)(n0 + (idx >> 3)) * ldb + ((idx & 7) << 2));
    }

    float c[2][4][4] = {};

    const int kiters = K >> 5;
    for (int it = 0; it < kiters; it++) {
        // store current tile to smem (convert to tf32)
#pragma unroll
        for (int i = 0; i < 4; i++) {
            int idx = tid + i * 256;
            unsigned* p = &As[(idx >> 3) * AST + ((idx & 7) << 2)];
            p[0] = f2tf32(la[i].x); p[1] = f2tf32(la[i].y);
            p[2] = f2tf32(la[i].z); p[3] = f2tf32(la[i].w);
        }
#pragma unroll
        for (int i = 0; i < 2; i++) {
            int idx = tid + i * 256;
            unsigned* p = &Bs[(idx >> 3) * BST + ((idx & 7) << 2)];
            p[0] = f2tf32(lb[i].x); p[1] = f2tf32(lb[i].y);
            p[2] = f2tf32(lb[i].z); p[3] = f2tf32(lb[i].w);
        }
        __syncthreads();

        // prefetch next tile
        if (it + 1 < kiters) {
            int kb = (it + 1) << 5;
#pragma unroll
            for (int i = 0; i < 4; i++) {
                int idx = tid + i * 256;
                la[i] = *(const float4*)(A + (long)(m0 + (idx >> 3)) * lda + kb + ((idx & 7) << 2));
            }
#pragma unroll
            for (int i = 0; i < 2; i++) {
                int idx = tid + i * 256;
                lb[i] = *(const float4*)(B + (long)(n0 + (idx >> 3)) * ldb + kb + ((idx & 7) << 2));
            }
        }

        // compute 4 k-steps of 8
#pragma unroll
        for (int kk = 0; kk < 4; kk++) {
            int kb = kk * 8;
            unsigned af[2][4], bf[4][2];
#pragma unroll
            for (int mf = 0; mf < 2; mf++) {
                int r0 = (wm * 32 + mf * 16 + g) * AST;
                af[mf][0] = As[r0 + kb + t];
                af[mf][1] = As[r0 + 8 * AST + kb + t];
                af[mf][2] = As[r0 + kb + t + 4];
                af[mf][3] = As[r0 + 8 * AST + kb + t + 4];
            }
#pragma unroll
            for (int nf = 0; nf < 4; nf++) {
                int r0 = (wn * 32 + nf * 8 + g) * BST;
                bf[nf][0] = Bs[r0 + kb + t];
                bf[nf][1] = Bs[r0 + kb + t + 4];
            }
#pragma unroll
            for (int mf = 0; mf < 2; mf++)
#pragma unroll
                for (int nf = 0; nf < 4; nf++)
                    mma_tf32(c[mf][nf][0], c[mf][nf][1], c[mf][nf][2], c[mf][nf][3],
                             af[mf][0], af[mf][1], af[mf][2], af[mf][3],
                             bf[nf][0], bf[nf][1]);
        }
        __syncthreads();
    }

    // epilogue
#pragma unroll
    for (int mf = 0; mf < 2; mf++) {
        int row = m0 + wm * 32 + mf * 16 + g;
#pragma unroll
        for (int nf = 0; nf < 4; nf++) {
            int col = n0 + wn * 32 + nf * 8 + 2 * t;
            *(float2*)(C + (long)row * ldc + col)       = make_float2(c[mf][nf][0], c[mf][nf][1]);
            *(float2*)(C + (long)(row + 8) * ldc + col) = make_float2(c[mf][nf][2], c[mf][nf][3]);
        }
    }
}

// ---------------------------------------------------------------------------
// tf32 MMA GEMM, NN: C[m,n] = sum_k A[m,k]*B[k,n]  (attn @ V)
// B tile stored [k][n] with stride 68 (==4 mod 32) -> conflict-free.
// ---------------------------------------------------------------------------
__global__ __launch_bounds__(256, 2) void gemm_nn_tc(
    const float* __restrict__ A, int lda, long aO, long aI,
    const float* __restrict__ B, int ldb, long bO, long bI,
    float* __restrict__ C, int ldc, long cO, long cI,
    int K, int zdiv)
{
    int z = blockIdx.z;
    long zo = z / zdiv, zi = z % zdiv;
    A += zo * aO + zi * aI;
    B += zo * bO + zi * bI;
    C += zo * cO + zi * cI;

    __shared__ unsigned As[128 * AST];
    __shared__ unsigned Bs[32 * BSTN];

    const int tid  = threadIdx.x;
    const int warp = tid >> 5;
    const int lane = tid & 31;
    const int g = lane >> 2;
    const int t = lane & 3;
    const int wm = warp >> 1;
    const int wn = warp & 1;

    const int m0 = blockIdx.y * 128;
    const int n0 = blockIdx.x * 64;

    float4 la[4], lb[2];
#pragma unroll
    for (int i = 0; i < 4; i++) {
        int idx = tid + i * 256;
        la[i] = *(const float4*)(A + (long)(m0 + (idx >> 3)) * lda + ((idx & 7) << 2));
    }
#pragma unroll
    for (int i = 0; i < 2; i++) {
        int idx = tid + i * 256;
        lb[i] = *(const float4*)(B + (long)(idx >> 4) * ldb + n0 + ((idx & 15) << 2));
    }

    float c[2][4][4] = {};

    const int kiters = K >> 5;
    for (int it = 0; it < kiters; it++) {
#pragma unroll
        for (int i = 0; i < 4; i++) {
            int idx = tid + i * 256;
            unsigned* p = &As[(idx >> 3) * AST + ((idx & 7) << 2)];
            p[0] = f2tf32(la[i].x); p[1] = f2tf32(la[i].y);
            p[2] = f2tf32(la[i].z); p[3] = f2tf32(la[i].w);
        }
#pragma unroll
        for (int i = 0; i < 2; i++) {
            int idx = tid + i * 256;
            unsigned* p = &Bs[(idx >> 4) * BSTN + ((idx & 15) << 2)];
            p[0] = f2tf32(lb[i].x); p[1] = f2tf32(lb[i].y);
            p[2] = f2tf32(lb[i].z); p[3] = f2tf32(lb[i].w);
        }
        __syncthreads();

        if (it + 1 < kiters) {
            int kb = (it + 1) << 5;
#pragma unroll
            for (int i = 0; i < 4; i++) {
                int idx = tid + i * 256;
                la[i] = *(const float4*)(A + (long)(m0 + (idx >> 3)) * lda + kb + ((idx & 7) << 2));
            }
#pragma unroll
            for (int i = 0; i < 2; i++) {
                int idx = tid + i * 256;
                lb[i] = *(const float4*)(B + (long)(kb + (idx >> 4)) * ldb + n0 + ((idx & 15) << 2));
            }
        }

#pragma unroll
        for (int kk = 0; kk < 4; kk++) {
            int kb = kk * 8;
            unsigned af[2][4], bf[4][2];
#pragma unroll
            for (int mf = 0; mf < 2; mf++) {
                int r0 = (wm * 32 + mf * 16 + g) * AST;
                af[mf][0] = As[r0 + kb + t];
                af[mf][1] = As[r0 + 8 * AST + kb + t];
                af[mf][2] = As[r0 + kb + t + 4];
                af[mf][3] = As[r0 + 8 * AST + kb + t + 4];
            }
#pragma unroll
            for (int nf = 0; nf < 4; nf++) {
                int cn = wn * 32 + nf * 8 + g;
                bf[nf][0] = Bs[(kb + t) * BSTN + cn];
                bf[nf][1] = Bs[(kb + t + 4) * BSTN + cn];
            }
#pragma unroll
            for (int mf = 0; mf < 2; mf++)
#pragma unroll
                for (int nf = 0; nf < 4; nf++)
                    mma_tf32(c[mf][nf][0], c[mf][nf][1], c[mf][nf][2], c[mf][nf][3],
                             af[mf][0], af[mf][1], af[mf][2], af[mf][3],
                             bf[nf][0], bf[nf][1]);
        }
        __syncthreads();
    }

#pragma unroll
    for (int mf = 0; mf < 2; mf++) {
        int row = m0 + wm * 32 + mf * 16 + g;
#pragma unroll
        for (int nf = 0; nf < 4; nf++) {
            int col = n0 + wn * 32 + nf * 8 + 2 * t;
            *(float2*)(C + (long)row * ldc + col)       = make_float2(c[mf][nf][0], c[mf][nf][1]);
            *(float2*)(C + (long)(row + 8) * ldc + col) = make_float2(c[mf][nf][2], c[mf][nf][3]);
        }
    }
}

// q + pos_bias_u / q + pos_bias_v
__global__ void add_bias2(const float* __restrict__ q,
                          const float* __restrict__ u,
                          const float* __restrict__ v,
                          float* __restrict__ qu, float* __restrict__ qv, int n)
{
    int i = blockIdx.x * blockDim.x + threadIdx.x;
    if (i < n) {
        float b = q[i];
        int c = i & (DM - 1);
        qu[i] = b + u[c];
        qv[i] = b + v[c];
    }
}

// Fused rel-shift gather + scale + softmax (one block per (b,h,i) row)
__global__ __launch_bounds__(256) void softmax_shift(
    float* __restrict__ scores, const float* __restrict__ rel)
{
    int row = blockIdx.x;
    int z = row >> 10;
    int i = row & (TT - 1);
    float* crow = scores + (size_t)row * LL;
    const float* rz = rel + (size_t)z * TT * JJ;

    int tid = threadIdx.x;
    float vals[8];
    float mx = -1e30f;
#pragma unroll
    for (int t = 0; t < 8; t++) {
        int l = tid + t * 256;
        long idx = (long)i * JJ + l + TT;
        int rr = (int)(idx / (JJ + 1));
        int cc = (int)(idx - (long)rr * (JJ + 1));
        float rv = (cc != 0) ? rz[(size_t)rr * JJ + (cc - 1)] : 0.0f;
        float s = (crow[l] + rv) * SCALE_F;
        vals[t] = s;
        mx = fmaxf(mx, s);
    }

    __shared__ float red[256];
    red[tid] = mx;
    __syncthreads();
    for (int s = 128; s > 0; s >>= 1) {
        if (tid < s) red[tid] = fmaxf(red[tid], red[tid + s]);
        __syncthreads();
    }
    mx = red[0];
    __syncthreads();

    float sum = 0.0f;
#pragma unroll
    for (int t = 0; t < 8; t++) {
        vals[t] = __expf(vals[t] - mx);
        sum += vals[t];
    }
    red[tid] = sum;
    __syncthreads();
    for (int s = 128; s > 0; s >>= 1) {
        if (tid < s) red[tid] += red[tid + s];
        __syncthreads();
    }
    float inv = 1.0f / red[0];
#pragma unroll
    for (int t = 0; t < 8; t++) {
        int l = tid + t * 256;
        crow[l] = vals[t] * inv;
    }
}

extern "C" void kernel_launch(void* const* d_in, const int* in_sizes, int n_in,
                              void* d_out, int out_size)
{
    (void)in_sizes; (void)n_in; (void)out_size;
    const float* x      = (const float*)d_in[0];
    const float* memory = (const float*)d_in[1];
    const float* pos    = (const float*)d_in[2];
    const float* q_w    = (const float*)d_in[3];
    const float* k_w    = (const float*)d_in[4];
    const float* v_w    = (const float*)d_in[5];
    const float* r_w    = (const float*)d_in[6];
    const float* out_w  = (const float*)d_in[7];
    const float* pb_u   = (const float*)d_in[8];
    const float* pb_v   = (const float*)d_in[9];
    float* out = (float*)d_out;

    float *qraw, *qu, *qv, *kraw, *vraw, *rraw, *scores, *rel, *ctx;
    cudaGetSymbolAddress((void**)&qraw,   g_qraw);
    cudaGetSymbolAddress((void**)&qu,     g_qu);
    cudaGetSymbolAddress((void**)&qv,     g_qv);
    cudaGetSymbolAddress((void**)&kraw,   g_kraw);
    cudaGetSymbolAddress((void**)&vraw,   g_vraw);
    cudaGetSymbolAddress((void**)&rraw,   g_rraw);
    cudaGetSymbolAddress((void**)&scores, g_scores);
    cudaGetSymbolAddress((void**)&rel,    g_rel);
    cudaGetSymbolAddress((void**)&ctx,    g_ctx);

    const long TD = (long)TT * DM;
    const long LD = (long)LL * DM;
    const long TL = (long)TT * LL;

    // 1) Q projection: [2048,1024] = x @ q_w.T
    gemm_nt_tc<<<dim3(DM / 64, (BB * TT) / 128, 1), 256>>>(
        x, DM, 0, 0,  q_w, DM, 0, 0,  qraw, DM, 0, 0,  DM, 1);

    // 2) K projection over cat = [memory; x] per batch
    gemm_nt_tc<<<dim3(DM / 64, MM / 128, BB), 256>>>(
        memory, DM, (long)MM * DM, 0,  k_w, DM, 0, 0,
        kraw, DM, LD, 0,  DM, 1);
    gemm_nt_tc<<<dim3(DM / 64, TT / 128, BB), 256>>>(
        x, DM, TD, 0,  k_w, DM, 0, 0,
        kraw + (long)MM * DM, DM, LD, 0,  DM, 1);

    // 3) V projection over cat
    gemm_nt_tc<<<dim3(DM / 64, MM / 128, BB), 256>>>(
        memory, DM, (long)MM * DM, 0,  v_w, DM, 0, 0,
        vraw, DM, LD, 0,  DM, 1);
    gemm_nt_tc<<<dim3(DM / 64, TT / 128, BB), 256>>>(
        x, DM, TD, 0,  v_w, DM, 0, 0,
        vraw + (long)MM * DM, DM, LD, 0,  DM, 1);

    // 4) R projection
    gemm_nt_tc<<<dim3(DM / 64, JJ / 128, 1), 256>>>(
        pos, DM, 0, 0,  r_w, DM, 0, 0,  rraw, DM, 0, 0,  DM, 1);

    // 5) q_u = q + u, q_v = q + v
    add_bias2<<<(BB * TT * DM) / 256, 256>>>(qraw, pb_u, pb_v, qu, qv, BB * TT * DM);

    // 6) content scores: per (b,h): [1024,2048] = (q+u) @ k^T
    gemm_nt_tc<<<dim3(LL / 64, TT / 128, BB * HH), 256>>>(
        qu,   DM, TD, 64,
        kraw, DM, LD, 64,
        scores, LL, (long)HH * TL, TL,
        DH, HH);

    // 7) rel scores: per (b,h): [1024,2048] = (q+v) @ r^T
    gemm_nt_tc<<<dim3(JJ / 64, TT / 128, BB * HH), 256>>>(
        qv,   DM, TD, 64,
        rraw, DM, 0,  64,
        rel, JJ, (long)HH * TL, TL,
        DH, HH);

    // 8) rel-shift + scale + softmax (in place on scores)
    softmax_shift<<<BB * HH * TT, 256>>>(scores, rel);

    // 9) ctx = attn @ V
    gemm_nn_tc<<<dim3(1, TT / 128, BB * HH), 256>>>(
        scores, LL, (long)HH * TL, TL,
        vraw,   DM, LD, 64,
        ctx,    DM, TD, 64,
        LL, HH);

    // 10) output projection
    gemm_nt_tc<<<dim3(DM / 64, (BB * TT) / 128, 1), 256>>>(
        ctx, DM, 0, 0,  out_w, DM, 0, 0,  out, DM, 0, 0,  DM, 1);
}

// round 5
// speedup vs baseline: 4.1148x; 1.5455x over previous
#include <cuda_runtime.h>
#include <cuda_fp16.h>
#include <cstdint>

#define BB 2
#define TT 1024
#define MM 1024
#define LL 2048
#define JJ 2048
#define HH 16
#define DH 64
#define DM 1024
#define SCALE_F 0.125f

// -------- scratch (device globals) --------
__device__ __half g_x16  [BB * TT * DM];
__device__ __half g_mem16[BB * MM * DM];
__device__ __half g_pos16[JJ * DM];
__device__ __half g_qw16 [DM * DM];
__device__ __half g_kw16 [DM * DM];
__device__ __half g_vw16 [DM * DM];
__device__ __half g_rw16 [DM * DM];
__device__ __half g_ow16 [DM * DM];
__device__ __half g_q16  [BB * TT * DM];
__device__ __half g_qu16 [BB * TT * DM];
__device__ __half g_qv16 [BB * TT * DM];
__device__ __half g_k16  [BB * LL * DM];
__device__ __half g_v16  [BB * LL * DM];
__device__ __half g_r16  [JJ * DM];
__device__ __half g_ctx16[BB * TT * DM];
__device__ float  g_scores[(size_t)BB * HH * TT * LL];
__device__ float  g_rel   [(size_t)BB * HH * TT * JJ];
__device__ __half g_probs [(size_t)BB * HH * TT * LL];

// ---------------- PTX helpers ----------------
__device__ __forceinline__ uint32_t smem_u32(const void* p) {
    return (uint32_t)__cvta_generic_to_shared(p);
}
__device__ __forceinline__ void cp16(uint32_t s, const void* g) {
    asm volatile("cp.async.cg.shared.global [%0], [%1], 16;" :: "r"(s), "l"(g));
}
__device__ __forceinline__ void cp_commit() {
    asm volatile("cp.async.commit_group;");
}
template <int N> __device__ __forceinline__ void cp_wait() {
    asm volatile("cp.async.wait_group %0;" :: "n"(N));
}
__device__ __forceinline__ void ldsm4(unsigned& r0, unsigned& r1, unsigned& r2, unsigned& r3, uint32_t a) {
    asm volatile("ldmatrix.sync.aligned.m8n8.x4.shared.b16 {%0,%1,%2,%3},[%4];"
                 : "=r"(r0), "=r"(r1), "=r"(r2), "=r"(r3) : "r"(a));
}
__device__ __forceinline__ void ldsm4t(unsigned& r0, unsigned& r1, unsigned& r2, unsigned& r3, uint32_t a) {
    asm volatile("ldmatrix.sync.aligned.m8n8.x4.trans.shared.b16 {%0,%1,%2,%3},[%4];"
                 : "=r"(r0), "=r"(r1), "=r"(r2), "=r"(r3) : "r"(a));
}
__device__ __forceinline__ void mma_f16(float& c0, float& c1, float& c2, float& c3,
                                        unsigned a0, unsigned a1, unsigned a2, unsigned a3,
                                        unsigned b0, unsigned b1) {
    asm volatile(
        "mma.sync.aligned.m16n8k16.row.col.f32.f16.f16.f32 "
        "{%0,%1,%2,%3}, {%4,%5,%6,%7}, {%8,%9}, {%0,%1,%2,%3};"
        : "+f"(c0), "+f"(c1), "+f"(c2), "+f"(c3)
        : "r"(a0), "r"(a1), "r"(a2), "r"(a3), "r"(b0), "r"(b1));
}

template <typename OutT>
__device__ __forceinline__ void store_c2(OutT* p, float a, float b);
template <> __device__ __forceinline__ void store_c2<float>(float* p, float a, float b) {
    *(float2*)p = make_float2(a, b);
}
template <> __device__ __forceinline__ void store_c2<__half>(__half* p, float a, float b) {
    *(__half2*)p = __floats2half2_rn(a, b);
}

// ---------------------------------------------------------------------------
// fp16 MMA GEMM, NT: C[m,n] = sum_k A[m,k]*B[n,k]. BM=128 BN=128 BK=32.
// 256 threads, 8 warps (2 M x 4 N), warp tile 64x32 (mf=4, nf=4).
// cp.async double buffer, ldmatrix.x4 fragment loads, 80B smem rows.
// ---------------------------------------------------------------------------
#define ROWH 40          // halfs per smem row (80 bytes)
#define STG_NT (128 * ROWH * 2)   // bytes per stage

template <typename OutT>
__global__ __launch_bounds__(256, 2) void gemm_nt_f16(
    const __half* __restrict__ A, int lda, long aO, long aI,
    const __half* __restrict__ B, int ldb, long bO, long bI,
    OutT* __restrict__ C, int ldc, long cO, long cI,
    int K, int zdiv)
{
    int z = blockIdx.z;
    long zo = z / zdiv, zi = z % zdiv;
    A += zo * aO + zi * aI;
    B += zo * bO + zi * bI;
    C += zo * cO + zi * cI;

    __shared__ __align__(16) __half As[2][128][ROWH];
    __shared__ __align__(16) __half Bs[2][128][ROWH];

    const int tid  = threadIdx.x;
    const int warp = tid >> 5;
    const int lane = tid & 31;
    const int g = lane >> 2, t = lane & 3;
    const int wm = warp >> 2;       // 0..1 -> m offset wm*64
    const int wn = warp & 3;        // 0..3 -> n offset wn*32

    const int m0 = blockIdx.y * 128;
    const int n0 = blockIdx.x * 128;

    // loaders: each thread 2 chunks (32B) of A and of B
    const int lrow = tid >> 1;
    const int lcw  = (tid & 1) * 2;          // 16B-chunk index 0 or 2
    const __half* Ag = A + (long)(m0 + lrow) * lda + lcw * 8;
    const __half* Bg = B + (long)(n0 + lrow) * ldb + lcw * 8;
    const uint32_t aSm = smem_u32(&As[0][lrow][lcw * 8]);
    const uint32_t bSm = smem_u32(&Bs[0][lrow][lcw * 8]);

    // ldmatrix base addresses
    const int rowA = wm * 64 + (lane & 15);
    const int colA = ((lane >> 4) & 1) * 8;
    const uint32_t aLd = smem_u32(&As[0][rowA][colA]);
    const int rowB = wn * 32 + ((lane >> 4) & 1) * 8 + (lane & 7);
    const int colB = ((lane >> 3) & 1) * 8;
    const uint32_t bLd = smem_u32(&Bs[0][rowB][colB]);

    float acc[4][4][4] = {};

    const int kiters = K >> 5;
    // preload stage 0
    {
        cp16(aSm, Ag);        cp16(aSm + 16, Ag + 8);
        cp16(bSm, Bg);        cp16(bSm + 16, Bg + 8);
        cp_commit();
    }

    for (int it = 0; it < kiters; it++) {
        const int cur = it & 1;
        if (it + 1 < kiters) {
            const int nxt = (it + 1) & 1;
            const __half* ag = Ag + (long)(it + 1) * 32;
            const __half* bg = Bg + (long)(it + 1) * 32;
            cp16(aSm + nxt * STG_NT, ag);      cp16(aSm + nxt * STG_NT + 16, ag + 8);
            cp16(bSm + nxt * STG_NT, bg);      cp16(bSm + nxt * STG_NT + 16, bg + 8);
            cp_commit();
            cp_wait<1>();
        } else {
            cp_wait<0>();
        }
        __syncthreads();

#pragma unroll
        for (int kk = 0; kk < 2; kk++) {
            unsigned af[4][4], bf[4][2];
#pragma unroll
            for (int mf = 0; mf < 4; mf++)
                ldsm4(af[mf][0], af[mf][1], af[mf][2], af[mf][3],
                      aLd + cur * STG_NT + mf * (16 * ROWH * 2) + kk * 32);
#pragma unroll
            for (int nfp = 0; nfp < 2; nfp++)
                ldsm4(bf[nfp * 2][0], bf[nfp * 2][1], bf[nfp * 2 + 1][0], bf[nfp * 2 + 1][1],
                      bLd + cur * STG_NT + nfp * (16 * ROWH * 2) + kk * 32);
#pragma unroll
            for (int mf = 0; mf < 4; mf++)
#pragma unroll
                for (int nf = 0; nf < 4; nf++)
                    mma_f16(acc[mf][nf][0], acc[mf][nf][1], acc[mf][nf][2], acc[mf][nf][3],
                            af[mf][0], af[mf][1], af[mf][2], af[mf][3],
                            bf[nf][0], bf[nf][1]);
        }
        __syncthreads();
    }

#pragma unroll
    for (int mf = 0; mf < 4; mf++) {
        int row = m0 + wm * 64 + mf * 16 + g;
#pragma unroll
        for (int nf = 0; nf < 4; nf++) {
            int col = n0 + wn * 32 + nf * 8 + 2 * t;
            store_c2<OutT>(C + (long)row * ldc + col,       acc[mf][nf][0], acc[mf][nf][1]);
            store_c2<OutT>(C + (long)(row + 8) * ldc + col, acc[mf][nf][2], acc[mf][nf][3]);
        }
    }
}

// ---------------------------------------------------------------------------
// fp16 MMA GEMM, NN: C[m,n] = sum_k A[m,k]*B[k,n]  (attn @ V), BN=64.
// 8 warps (2 M x 4 N), warp tile 64x16 (mf=4, nf=2). B frag via ldmatrix.trans.
// ---------------------------------------------------------------------------
#define ROWB 72          // halfs per B smem row (144 bytes, 64 data)
#define STG_B (32 * ROWB * 2)

__global__ __launch_bounds__(256, 2) void gemm_nn_f16(
    const __half* __restrict__ A, int lda, long aO, long aI,
    const __half* __restrict__ B, int ldb, long bO, long bI,
    __half* __restrict__ C, int ldc, long cO, long cI,
    int K, int zdiv)
{
    int z = blockIdx.z;
    long zo = z / zdiv, zi = z % zdiv;
    A += zo * aO + zi * aI;
    B += zo * bO + zi * bI;
    C += zo * cO + zi * cI;

    __shared__ __align__(16) __half As[2][128][ROWH];
    __shared__ __align__(16) __half Bs[2][32][ROWB];

    const int tid  = threadIdx.x;
    const int warp = tid >> 5;
    const int lane = tid & 31;
    const int g = lane >> 2, t = lane & 3;
    const int wm = warp >> 2;       // 0..1
    const int wn = warp & 3;        // 0..3 -> n offset wn*16

    const int m0 = blockIdx.y * 128;
    const int n0 = blockIdx.x * 64;

    const int lrow = tid >> 1;
    const int lcw  = (tid & 1) * 2;
    const __half* Ag = A + (long)(m0 + lrow) * lda + lcw * 8;
    const uint32_t aSm = smem_u32(&As[0][lrow][lcw * 8]);

    const int brow = tid >> 3;           // 0..31 (k)
    const int bcw  = tid & 7;            // 16B chunk within 64-half row
    const __half* Bg = B + (long)brow * ldb + n0 + bcw * 8;
    const uint32_t bSm = smem_u32(&Bs[0][brow][bcw * 8]);

    const int rowA = wm * 64 + (lane & 15);
    const int colA = ((lane >> 4) & 1) * 8;
    const uint32_t aLd = smem_u32(&As[0][rowA][colA]);
    const int rowBk = ((lane >> 3) & 1) * 8 + (lane & 7);
    const int colBn = wn * 16 + ((lane >> 4) & 1) * 8;
    const uint32_t bLd = smem_u32(&Bs[0][rowBk][colBn]);

    float acc[4][2][4] = {};

    const int kiters = K >> 5;
    {
        cp16(aSm, Ag);  cp16(aSm + 16, Ag + 8);
        cp16(bSm, Bg);
        cp_commit();
    }

    for (int it = 0; it < kiters; it++) {
        const int cur = it & 1;
        if (it + 1 < kiters) {
            const int nxt = (it + 1) & 1;
            const __half* ag = Ag + (long)(it + 1) * 32;
            const __half* bg = Bg + (long)(it + 1) * 32 * ldb;
            cp16(aSm + nxt * STG_NT, ag);  cp16(aSm + nxt * STG_NT + 16, ag + 8);
            cp16(bSm + nxt * STG_B, bg);
            cp_commit();
            cp_wait<1>();
        } else {
            cp_wait<0>();
        }
        __syncthreads();

#pragma unroll
        for (int kk = 0; kk < 2; kk++) {
            unsigned af[4][4], bf[2][2];
#pragma unroll
            for (int mf = 0; mf < 4; mf++)
                ldsm4(af[mf][0], af[mf][1], af[mf][2], af[mf][3],
                      aLd + cur * STG_NT + mf * (16 * ROWH * 2) + kk * 32);
            ldsm4t(bf[0][0], bf[0][1], bf[1][0], bf[1][1],
                   bLd + cur * STG_B + kk * (16 * ROWB * 2));
#pragma unroll
            for (int mf = 0; mf < 4; mf++)
#pragma unroll
                for (int nf = 0; nf < 2; nf++)
                    mma_f16(acc[mf][nf][0], acc[mf][nf][1], acc[mf][nf][2], acc[mf][nf][3],
                            af[mf][0], af[mf][1], af[mf][2], af[mf][3],
                            bf[nf][0], bf[nf][1]);
        }
        __syncthreads();
    }

#pragma unroll
    for (int mf = 0; mf < 4; mf++) {
        int row = m0 + wm * 64 + mf * 16 + g;
#pragma unroll
        for (int nf = 0; nf < 2; nf++) {
            int col = n0 + wn * 16 + nf * 8 + 2 * t;
            store_c2<__half>(C + (long)row * ldc + col,       acc[mf][nf][0], acc[mf][nf][1]);
            store_c2<__half>(C + (long)(row + 8) * ldc + col, acc[mf][nf][2], acc[mf][nf][3]);
        }
    }
}

// fp32 -> fp16 conversion, vectorized x4
__global__ void f2h(const float* __restrict__ in, __half* __restrict__ out, int n4)
{
    int i = blockIdx.x * blockDim.x + threadIdx.x;
    if (i < n4) {
        float4 v = ((const float4*)in)[i];
        __half2* o = (__half2*)out + i * 2;
        o[0] = __floats2half2_rn(v.x, v.y);
        o[1] = __floats2half2_rn(v.z, v.w);
    }
}

// q + pos_bias_u / q + pos_bias_v  (fp16 in/out, fp32 bias)
__global__ void add_bias2_h(const __half* __restrict__ q,
                            const float* __restrict__ u,
                            const float* __restrict__ v,
                            __half* __restrict__ qu, __half* __restrict__ qv, int n)
{
    int i = blockIdx.x * blockDim.x + threadIdx.x;
    if (i < n) {
        float b = __half2float(q[i]);
        int c = i & (DM - 1);
        qu[i] = __float2half_rn(b + u[c]);
        qv[i] = __float2half_rn(b + v[c]);
    }
}

// Fused rel-shift gather + scale + softmax; writes fp16 probs.
__global__ __launch_bounds__(256) void softmax_shift(
    const float* __restrict__ scores, const float* __restrict__ rel,
    __half* __restrict__ probs)
{
    int row = blockIdx.x;
    int z = row >> 10;
    int i = row & (TT - 1);
    const float* crow = scores + (size_t)row * LL;
    __half* prow = probs + (size_t)row * LL;
    const float* rz = rel + (size_t)z * TT * JJ;

    int tid = threadIdx.x;
    float vals[8];
    float mx = -1e30f;
#pragma unroll
    for (int tt = 0; tt < 8; tt++) {
        int l = tid + tt * 256;
        long idx = (long)i * JJ + l + TT;
        int rr = (int)(idx / (JJ + 1));
        int cc = (int)(idx - (long)rr * (JJ + 1));
        float rv = (cc != 0) ? rz[(size_t)rr * JJ + (cc - 1)] : 0.0f;
        float s = (crow[l] + rv) * SCALE_F;
        vals[tt] = s;
        mx = fmaxf(mx, s);
    }

    __shared__ float red[256];
    red[tid] = mx;
    __syncthreads();
    for (int s = 128; s > 0; s >>= 1) {
        if (tid < s) red[tid] = fmaxf(red[tid], red[tid + s]);
        __syncthreads();
    }
    mx = red[0];
    __syncthreads();

    float sum = 0.0f;
#pragma unroll
    for (int tt = 0; tt < 8; tt++) {
        vals[tt] = __expf(vals[tt] - mx);
        sum += vals[tt];
    }
    red[tid] = sum;
    __syncthreads();
    for (int s = 128; s > 0; s >>= 1) {
        if (tid < s) red[tid] += red[tid + s];
        __syncthreads();
    }
    float inv = 1.0f / red[0];
#pragma unroll
    for (int tt = 0; tt < 8; tt++) {
        int l = tid + tt * 256;
        prow[l] = __float2half_rn(vals[tt] * inv);
    }
}

extern "C" void kernel_launch(void* const* d_in, const int* in_sizes, int n_in,
                              void* d_out, int out_size)
{
    (void)in_sizes; (void)n_in; (void)out_size;
    const float* x      = (const float*)d_in[0];
    const float* memory = (const float*)d_in[1];
    const float* pos    = (const float*)d_in[2];
    const float* q_w    = (const float*)d_in[3];
    const float* k_w    = (const float*)d_in[4];
    const float* v_w    = (const float*)d_in[5];
    const float* r_w    = (const float*)d_in[6];
    const float* out_w  = (const float*)d_in[7];
    const float* pb_u   = (const float*)d_in[8];
    const float* pb_v   = (const float*)d_in[9];
    float* out = (float*)d_out;

    __half *x16, *mem16, *pos16, *qw16, *kw16, *vw16, *rw16, *ow16;
    __half *q16, *qu16, *qv16, *k16, *v16, *r16, *ctx16, *probs;
    float *scores, *rel;
    cudaGetSymbolAddress((void**)&x16,   g_x16);
    cudaGetSymbolAddress((void**)&mem16, g_mem16);
    cudaGetSymbolAddress((void**)&pos16, g_pos16);
    cudaGetSymbolAddress((void**)&qw16,  g_qw16);
    cudaGetSymbolAddress((void**)&kw16,  g_kw16);
    cudaGetSymbolAddress((void**)&vw16,  g_vw16);
    cudaGetSymbolAddress((void**)&rw16,  g_rw16);
    cudaGetSymbolAddress((void**)&ow16,  g_ow16);
    cudaGetSymbolAddress((void**)&q16,   g_q16);
    cudaGetSymbolAddress((void**)&qu16,  g_qu16);
    cudaGetSymbolAddress((void**)&qv16,  g_qv16);
    cudaGetSymbolAddress((void**)&k16,   g_k16);
    cudaGetSymbolAddress((void**)&v16,   g_v16);
    cudaGetSymbolAddress((void**)&r16,   g_r16);
    cudaGetSymbolAddress((void**)&ctx16, g_ctx16);
    cudaGetSymbolAddress((void**)&probs, g_probs);
    cudaGetSymbolAddress((void**)&scores, g_scores);
    cudaGetSymbolAddress((void**)&rel,    g_rel);

    const long TD = (long)TT * DM;
    const long LD = (long)LL * DM;
    const long TL = (long)TT * LL;

    // 0) fp32 -> fp16 conversions
    f2h<<<(BB * TT * DM / 4 + 255) / 256, 256>>>(x,      x16,   BB * TT * DM / 4);
    f2h<<<(BB * MM * DM / 4 + 255) / 256, 256>>>(memory, mem16, BB * MM * DM / 4);
    f2h<<<(JJ * DM / 4 + 255) / 256, 256>>>(pos,   pos16, JJ * DM / 4);
    f2h<<<(DM * DM / 4 + 255) / 256, 256>>>(q_w,   qw16,  DM * DM / 4);
    f2h<<<(DM * DM / 4 + 255) / 256, 256>>>(k_w,   kw16,  DM * DM / 4);
    f2h<<<(DM * DM / 4 + 255) / 256, 256>>>(v_w,   vw16,  DM * DM / 4);
    f2h<<<(DM * DM / 4 + 255) / 256, 256>>>(r_w,   rw16,  DM * DM / 4);
    f2h<<<(DM * DM / 4 + 255) / 256, 256>>>(out_w, ow16,  DM * DM / 4);

    // 1) Q projection: [2048,1024] = x @ q_w.T  -> fp16
    gemm_nt_f16<__half><<<dim3(DM / 128, (BB * TT) / 128, 1), 256>>>(
        x16, DM, 0, 0,  qw16, DM, 0, 0,  q16, DM, 0, 0,  DM, 1);

    // 2) K projection over cat = [memory; x] per batch
    gemm_nt_f16<__half><<<dim3(DM / 128, MM / 128, BB), 256>>>(
        mem16, DM, (long)MM * DM, 0,  kw16, DM, 0, 0,
        k16, DM, LD, 0,  DM, 1);
    gemm_nt_f16<__half><<<dim3(DM / 128, TT / 128, BB), 256>>>(
        x16, DM, TD, 0,  kw16, DM, 0, 0,
        k16 + (long)MM * DM, DM, LD, 0,  DM, 1);

    // 3) V projection over cat
    gemm_nt_f16<__half><<<dim3(DM / 128, MM / 128, BB), 256>>>(
        mem16, DM, (long)MM * DM, 0,  vw16, DM, 0, 0,
        v16, DM, LD, 0,  DM, 1);
    gemm_nt_f16<__half><<<dim3(DM / 128, TT / 128, BB), 256>>>(
        x16, DM, TD, 0,  vw16, DM, 0, 0,
        v16 + (long)MM * DM, DM, LD, 0,  DM, 1);

    // 4) R projection
    gemm_nt_f16<__half><<<dim3(DM / 128, JJ / 128, 1), 256>>>(
        pos16, DM, 0, 0,  rw16, DM, 0, 0,  r16, DM, 0, 0,  DM, 1);

    // 5) q_u = q + u, q_v = q + v
    add_bias2_h<<<(BB * TT * DM) / 256, 256>>>(q16, pb_u, pb_v, qu16, qv16, BB * TT * DM);

    // 6) content scores: per (b,h): [1024,2048] = (q+u) @ k^T  -> fp32
    gemm_nt_f16<float><<<dim3(LL / 128, TT / 128, BB * HH), 256>>>(
        qu16, DM, TD, 64,
        k16,  DM, LD, 64,
        scores, LL, (long)HH * TL, TL,
        DH, HH);

    // 7) rel scores: per (b,h): [1024,2048] = (q+v) @ r^T  -> fp32
    gemm_nt_f16<float><<<dim3(JJ / 128, TT / 128, BB * HH), 256>>>(
        qv16, DM, TD, 64,
        r16,  DM, 0,  64,
        rel, JJ, (long)HH * TL, TL,
        DH, HH);

    // 8) rel-shift + scale + softmax -> fp16 probs
    softmax_shift<<<BB * HH * TT, 256>>>(scores, rel, probs);

    // 9) ctx = attn @ V  (fp16 x fp16 -> fp16), per (b,h) into [B,T,D]
    gemm_nn_f16<<<dim3(1, TT / 128, BB * HH), 256>>>(
        probs, LL, (long)HH * TL, TL,
        v16,   DM, LD, 64,
        ctx16, DM, TD, 64,
        LL, HH);

    // 10) output projection -> fp32 out
    gemm_nt_f16<float><<<dim3(DM / 128, (BB * TT) / 128, 1), 256>>>(
        ctx16, DM, 0, 0,  ow16, DM, 0, 0,  out, DM, 0, 0,  DM, 1);
}